// round 1
// baseline (speedup 1.0000x reference)
#include <cuda_runtime.h>
#include <math.h>

#define NN 10000
#define EE 160000
#define BB 16
#define HH 64
#define AA 8
#define LL 2
#define MSGIN 131
#define UPDIN 129

// ---------------- scratch (device globals: no allocation allowed) ----------
__device__ float g_h[NN * HH];
__device__ float g_agg[NN * HH];
__device__ float g_pool[BB * HH];
__device__ float g_cnt[BB];

__device__ __forceinline__ float silu_f(float x) { return x / (1.0f + expf(-x)); }

// ---------------- shared memory layout (floats) ----------------------------
// s_W   : 32*8*64            = 16384
// s_in  : 256*33             =  8448   (padded stride 33 -> conflict-free)
// s_mid : 256*65             = 16640   (padded stride 65)
// s_a   : 256*8              =  2048
// s_idx : 512 ints           =   512
#define OFF_SW   0
#define OFF_SIN  16384
#define OFF_SMID (16384 + 8448)
#define OFF_SA   (16384 + 8448 + 16640)
#define OFF_SIDX (OFF_SA + 2048)
#define SMEM_FLOATS (OFF_SIDX + 512)
#define SMEM_BYTES (SMEM_FLOATS * 4)

// Core inner product over one i-tile. Each thread: 4 items x 16 outputs.
__device__ __forceinline__ void tp_accum(float (&acc)[4][16], const float* s_in, int stride,
                                         const float* s_W, const float (&av)[4][8],
                                         int e0, int kbase, int ilen)
{
    for (int i = 0; i < ilen; ++i) {
        float m0 = s_in[(e0 + 0) * stride + i];
        float m1 = s_in[(e0 + 1) * stride + i];
        float m2 = s_in[(e0 + 2) * stride + i];
        float m3 = s_in[(e0 + 3) * stride + i];
        const float* wrow = s_W + i * 512 + kbase;
#pragma unroll
        for (int j = 0; j < 8; ++j) {
            float4 wa = *(const float4*)(wrow + j * 64);
            float4 wb = *(const float4*)(wrow + j * 64 + 4);
            float4 wc = *(const float4*)(wrow + j * 64 + 8);
            float4 wd = *(const float4*)(wrow + j * 64 + 12);
            float w[16] = {wa.x, wa.y, wa.z, wa.w, wb.x, wb.y, wb.z, wb.w,
                           wc.x, wc.y, wc.z, wc.w, wd.x, wd.y, wd.z, wd.w};
            float c0 = m0 * av[0][j];
            float c1 = m1 * av[1][j];
            float c2 = m2 * av[2][j];
            float c3 = m3 * av[3][j];
#pragma unroll
            for (int k = 0; k < 16; ++k) {
                acc[0][k] = fmaf(c0, w[k], acc[0][k]);
                acc[1][k] = fmaf(c1, w[k], acc[1][k]);
                acc[2][k] = fmaf(c2, w[k], acc[2][k]);
                acc[3][k] = fmaf(c3, w[k], acc[3][k]);
            }
        }
    }
}

__device__ __forceinline__ void load_w_tile(float* s_W, const float* Wg, int ibase, int ilen)
{
    const float4* src = (const float4*)(Wg + (size_t)ibase * 512);
    float4* dst = (float4*)s_W;
    int n4 = ilen * 128;
    for (int idx = threadIdx.x; idx < n4; idx += 256) dst[idx] = src[idx];
}

// ---------------- edge message kernel: silu(TP131) -> silu(TP64) -> scatter -
__global__ void __launch_bounds__(256, 1)
msg_kernel(int l, const int* __restrict__ edge_index, const float* __restrict__ edge_attr,
           const float* __restrict__ amf, const float* __restrict__ anf,
           const float* __restrict__ Wm1, const float* __restrict__ bm1,
           const float* __restrict__ Wm2, const float* __restrict__ bm2)
{
    extern __shared__ float sm[];
    float* s_W = sm + OFF_SW;
    float* s_in = sm + OFF_SIN;
    float* s_mid = sm + OFF_SMID;
    float* s_a = sm + OFF_SA;
    int* s_src = (int*)(sm + OFF_SIDX);
    int* s_dst = s_src + 256;

    int tid = threadIdx.x;
    int e_abs0 = blockIdx.x * 256;

    s_src[tid] = edge_index[e_abs0 + tid];
    s_dst[tid] = edge_index[EE + e_abs0 + tid];
    for (int idx = tid; idx < 2048; idx += 256)
        s_a[idx] = edge_attr[(size_t)e_abs0 * 8 + idx];
    __syncthreads();

    int kg = tid & 3, ig = tid >> 2;
    int kbase = kg * 16, e0 = ig * 4;
    float av[4][8];
#pragma unroll
    for (int s = 0; s < 4; ++s)
#pragma unroll
        for (int j = 0; j < 8; ++j) av[s][j] = s_a[(e0 + s) * 8 + j];

    const float* W1 = Wm1 + (size_t)l * MSGIN * 512;
    const float* W2 = Wm2 + (size_t)l * 64 * 512;

    float acc[4][16];
#pragma unroll
    for (int k = 0; k < 16; ++k) {
        float b = bm1[l * 64 + kbase + k];
        acc[0][k] = b; acc[1][k] = b; acc[2][k] = b; acc[3][k] = b;
    }

    for (int ibase = 0; ibase < MSGIN; ibase += 32) {
        int ilen = min(32, MSGIN - ibase);
        load_w_tile(s_W, W1, ibase, ilen);
        for (int idx = tid; idx < 256 * ilen; idx += 256) {
            int e = idx / ilen, ii = idx - e * ilen;
            int i = ibase + ii;
            float v;
            if (i < 65) {
                int nd = s_dst[e];
                v = (i < 64) ? g_h[nd * 64 + i] : anf[nd];
            } else if (i < 130) {
                int ns = s_src[e];
                int i2 = i - 65;
                v = (i2 < 64) ? g_h[ns * 64 + i2] : anf[ns];
            } else {
                v = amf[e_abs0 + e];
            }
            s_in[e * 33 + ii] = v;
        }
        __syncthreads();
        tp_accum(acc, s_in, 33, s_W, av, e0, kbase, ilen);
        __syncthreads();
    }

#pragma unroll
    for (int s = 0; s < 4; ++s)
#pragma unroll
        for (int k = 0; k < 16; ++k)
            s_mid[(e0 + s) * 65 + kbase + k] = silu_f(acc[s][k]);
    __syncthreads();

#pragma unroll
    for (int k = 0; k < 16; ++k) {
        float b = bm2[l * 64 + kbase + k];
        acc[0][k] = b; acc[1][k] = b; acc[2][k] = b; acc[3][k] = b;
    }
    for (int ibase = 0; ibase < 64; ibase += 32) {
        load_w_tile(s_W, W2, ibase, 32);
        __syncthreads();
        tp_accum(acc, s_mid + ibase, 65, s_W, av, e0, kbase, 32);
        __syncthreads();
    }

#pragma unroll
    for (int s = 0; s < 4; ++s) {
        int nd = s_dst[e0 + s];
#pragma unroll
        for (int k = 0; k < 16; ++k)
            atomicAdd(&g_agg[nd * 64 + kbase + k], silu_f(acc[s][k]));
    }
}

// ---------------- embedding kernel: h = TP17(concat(x,anf), node_attr) -----
__global__ void __launch_bounds__(256, 1)
embed_kernel(const float* __restrict__ x, const float* __restrict__ anf,
             const float* __restrict__ node_attr,
             const float* __restrict__ W_emb, const float* __restrict__ b_emb)
{
    extern __shared__ float sm[];
    float* s_W = sm + OFF_SW;
    float* s_in = sm + OFF_SIN;
    float* s_a = sm + OFF_SA;

    int tid = threadIdx.x;
    int n0 = blockIdx.x * 256;

    for (int idx = tid; idx < 2048; idx += 256) {
        int e = idx >> 3, j = idx & 7;
        int n = min(n0 + e, NN - 1);
        s_a[idx] = node_attr[n * 8 + j];
    }
    load_w_tile(s_W, W_emb, 0, 17);
    for (int idx = tid; idx < 256 * 17; idx += 256) {
        int e = idx / 17, i = idx - e * 17;
        int n = min(n0 + e, NN - 1);
        s_in[e * 33 + i] = (i < 16) ? x[n * 16 + i] : anf[n];
    }
    __syncthreads();

    int kg = tid & 3, ig = tid >> 2;
    int kbase = kg * 16, e0 = ig * 4;
    float av[4][8];
#pragma unroll
    for (int s = 0; s < 4; ++s)
#pragma unroll
        for (int j = 0; j < 8; ++j) av[s][j] = s_a[(e0 + s) * 8 + j];

    float acc[4][16];
#pragma unroll
    for (int k = 0; k < 16; ++k) {
        float b = b_emb[kbase + k];
        acc[0][k] = b; acc[1][k] = b; acc[2][k] = b; acc[3][k] = b;
    }
    tp_accum(acc, s_in, 33, s_W, av, e0, kbase, 17);

#pragma unroll
    for (int s = 0; s < 4; ++s) {
        int n = n0 + e0 + s;
        if (n < NN) {
#pragma unroll
            for (int k = 0; k < 16; ++k) g_h[n * 64 + kbase + k] = acc[s][k];
        }
    }
}

// ---------------- node update: silu(TP129) -> TP64, residual ---------------
__global__ void __launch_bounds__(256, 1)
upd_kernel(int l, const float* __restrict__ node_attr, const float* __restrict__ anf,
           const float* __restrict__ Wu1, const float* __restrict__ bu1,
           const float* __restrict__ Wu2, const float* __restrict__ bu2)
{
    extern __shared__ float sm[];
    float* s_W = sm + OFF_SW;
    float* s_in = sm + OFF_SIN;
    float* s_mid = sm + OFF_SMID;
    float* s_a = sm + OFF_SA;

    int tid = threadIdx.x;
    int n0 = blockIdx.x * 256;

    for (int idx = tid; idx < 2048; idx += 256) {
        int e = idx >> 3, j = idx & 7;
        int n = min(n0 + e, NN - 1);
        s_a[idx] = node_attr[n * 8 + j];
    }
    __syncthreads();

    int kg = tid & 3, ig = tid >> 2;
    int kbase = kg * 16, e0 = ig * 4;
    float av[4][8];
#pragma unroll
    for (int s = 0; s < 4; ++s)
#pragma unroll
        for (int j = 0; j < 8; ++j) av[s][j] = s_a[(e0 + s) * 8 + j];

    const float* W1 = Wu1 + (size_t)l * UPDIN * 512;
    const float* W2 = Wu2 + (size_t)l * 64 * 512;

    float acc[4][16];
#pragma unroll
    for (int k = 0; k < 16; ++k) {
        float b = bu1[l * 64 + kbase + k];
        acc[0][k] = b; acc[1][k] = b; acc[2][k] = b; acc[3][k] = b;
    }

    for (int ibase = 0; ibase < UPDIN; ibase += 32) {
        int ilen = min(32, UPDIN - ibase);
        load_w_tile(s_W, W1, ibase, ilen);
        for (int idx = tid; idx < 256 * ilen; idx += 256) {
            int e = idx / ilen, ii = idx - e * ilen;
            int i = ibase + ii;
            int n = min(n0 + e, NN - 1);
            float v;
            if (i < 64) v = g_h[n * 64 + i];
            else if (i == 64) v = anf[n];
            else v = g_agg[n * 64 + (i - 65)];
            s_in[e * 33 + ii] = v;
        }
        __syncthreads();
        tp_accum(acc, s_in, 33, s_W, av, e0, kbase, ilen);
        __syncthreads();
    }

#pragma unroll
    for (int s = 0; s < 4; ++s)
#pragma unroll
        for (int k = 0; k < 16; ++k)
            s_mid[(e0 + s) * 65 + kbase + k] = silu_f(acc[s][k]);
    __syncthreads();

#pragma unroll
    for (int k = 0; k < 16; ++k) {
        float b = bu2[l * 64 + kbase + k];
        acc[0][k] = b; acc[1][k] = b; acc[2][k] = b; acc[3][k] = b;
    }
    for (int ibase = 0; ibase < 64; ibase += 32) {
        load_w_tile(s_W, W2, ibase, 32);
        __syncthreads();
        tp_accum(acc, s_mid + ibase, 65, s_W, av, e0, kbase, 32);
        __syncthreads();
    }

#pragma unroll
    for (int s = 0; s < 4; ++s) {
        int n = n0 + e0 + s;
        if (n < NN) {
#pragma unroll
            for (int k = 0; k < 16; ++k)
                g_h[n * 64 + kbase + k] += acc[s][k];
        }
    }
}

// ---------------- pre-pool MLP + graph mean-pool scatter -------------------
__global__ void __launch_bounds__(256, 1)
pool_kernel(const float* __restrict__ node_attr, const int* __restrict__ batch,
            const float* __restrict__ Wp1, const float* __restrict__ bp1,
            const float* __restrict__ Wp2, const float* __restrict__ bp2)
{
    extern __shared__ float sm[];
    float* s_W = sm + OFF_SW;
    float* s_in = sm + OFF_SIN;
    float* s_mid = sm + OFF_SMID;
    float* s_a = sm + OFF_SA;

    int tid = threadIdx.x;
    int n0 = blockIdx.x * 256;

    for (int idx = tid; idx < 2048; idx += 256) {
        int e = idx >> 3, j = idx & 7;
        int n = min(n0 + e, NN - 1);
        s_a[idx] = node_attr[n * 8 + j];
    }
    __syncthreads();

    int kg = tid & 3, ig = tid >> 2;
    int kbase = kg * 16, e0 = ig * 4;
    float av[4][8];
#pragma unroll
    for (int s = 0; s < 4; ++s)
#pragma unroll
        for (int j = 0; j < 8; ++j) av[s][j] = s_a[(e0 + s) * 8 + j];

    float acc[4][16];
#pragma unroll
    for (int k = 0; k < 16; ++k) {
        float b = bp1[kbase + k];
        acc[0][k] = b; acc[1][k] = b; acc[2][k] = b; acc[3][k] = b;
    }
    for (int ibase = 0; ibase < 64; ibase += 32) {
        load_w_tile(s_W, Wp1, ibase, 32);
        for (int idx = tid; idx < 256 * 32; idx += 256) {
            int e = idx >> 5, ii = idx & 31;
            int n = min(n0 + e, NN - 1);
            s_in[e * 33 + ii] = g_h[n * 64 + ibase + ii];
        }
        __syncthreads();
        tp_accum(acc, s_in, 33, s_W, av, e0, kbase, 32);
        __syncthreads();
    }

#pragma unroll
    for (int s = 0; s < 4; ++s)
#pragma unroll
        for (int k = 0; k < 16; ++k)
            s_mid[(e0 + s) * 65 + kbase + k] = silu_f(acc[s][k]);
    __syncthreads();

#pragma unroll
    for (int k = 0; k < 16; ++k) {
        float b = bp2[kbase + k];
        acc[0][k] = b; acc[1][k] = b; acc[2][k] = b; acc[3][k] = b;
    }
    for (int ibase = 0; ibase < 64; ibase += 32) {
        load_w_tile(s_W, Wp2, ibase, 32);
        __syncthreads();
        tp_accum(acc, s_mid + ibase, 65, s_W, av, e0, kbase, 32);
        __syncthreads();
    }

#pragma unroll
    for (int s = 0; s < 4; ++s) {
        int n = n0 + e0 + s;
        if (n < NN) {
            int b = batch[n];
#pragma unroll
            for (int k = 0; k < 16; ++k)
                atomicAdd(&g_pool[b * 64 + kbase + k], acc[s][k]);
            if (kg == 0) atomicAdd(&g_cnt[b], 1.0f);
        }
    }
}

// ---------------- final tiny post-pool MLP ---------------------------------
__global__ void final_kernel(const float* __restrict__ Wq1, const float* __restrict__ bq1,
                             const float* __restrict__ Wq2, const float* __restrict__ bq2,
                             float* __restrict__ out)
{
    int b = threadIdx.x;
    if (b >= BB) return;
    float c = g_cnt[b];
    if (c < 1.0f) c = 1.0f;
    float g[64];
#pragma unroll
    for (int k = 0; k < 64; ++k) g[k] = g_pool[b * 64 + k] / c;
    float o = bq2[0];
    for (int j = 0; j < 64; ++j) {
        float s = bq1[j];
#pragma unroll
        for (int k = 0; k < 64; ++k) s = fmaf(g[k], Wq1[k * 64 + j], s);
        o = fmaf(silu_f(s), Wq2[j], o);
    }
    out[b] = o;
}

// ---------------- launch ----------------------------------------------------
extern "C" void kernel_launch(void* const* d_in, const int* in_sizes, int n_in,
                              void* d_out, int out_size)
{
    const float* x         = (const float*)d_in[0];
    const int*   edge_index= (const int*)d_in[1];
    const float* edge_attr = (const float*)d_in[2];
    const float* node_attr = (const float*)d_in[3];
    const float* amf       = (const float*)d_in[4];
    const float* anf       = (const float*)d_in[5];
    const int*   batch     = (const int*)d_in[6];
    const float* W_emb     = (const float*)d_in[7];
    const float* b_emb     = (const float*)d_in[8];
    const float* Wm1       = (const float*)d_in[9];
    const float* bm1       = (const float*)d_in[10];
    const float* Wm2       = (const float*)d_in[11];
    const float* bm2       = (const float*)d_in[12];
    const float* Wu1       = (const float*)d_in[13];
    const float* bu1       = (const float*)d_in[14];
    const float* Wu2       = (const float*)d_in[15];
    const float* bu2       = (const float*)d_in[16];
    const float* Wp1       = (const float*)d_in[17];
    const float* bp1       = (const float*)d_in[18];
    const float* Wp2       = (const float*)d_in[19];
    const float* bp2       = (const float*)d_in[20];
    const float* Wq1       = (const float*)d_in[21];
    const float* bq1       = (const float*)d_in[22];
    const float* Wq2       = (const float*)d_in[23];
    const float* bq2       = (const float*)d_in[24];
    float* out = (float*)d_out;

    cudaFuncSetAttribute(msg_kernel,   cudaFuncAttributeMaxDynamicSharedMemorySize, SMEM_BYTES);
    cudaFuncSetAttribute(embed_kernel, cudaFuncAttributeMaxDynamicSharedMemorySize, SMEM_BYTES);
    cudaFuncSetAttribute(upd_kernel,   cudaFuncAttributeMaxDynamicSharedMemorySize, SMEM_BYTES);
    cudaFuncSetAttribute(pool_kernel,  cudaFuncAttributeMaxDynamicSharedMemorySize, SMEM_BYTES);

    void* aggp = nullptr;  cudaGetSymbolAddress(&aggp, g_agg);
    void* poolp = nullptr; cudaGetSymbolAddress(&poolp, g_pool);
    void* cntp = nullptr;  cudaGetSymbolAddress(&cntp, g_cnt);

    int nblocks = (NN + 255) / 256;   // 40
    int eblocks = EE / 256;           // 625

    embed_kernel<<<nblocks, 256, SMEM_BYTES>>>(x, anf, node_attr, W_emb, b_emb);

    for (int l = 0; l < LL; ++l) {
        cudaMemsetAsync(aggp, 0, (size_t)NN * HH * sizeof(float));
        msg_kernel<<<eblocks, 256, SMEM_BYTES>>>(l, edge_index, edge_attr, amf, anf,
                                                 Wm1, bm1, Wm2, bm2);
        upd_kernel<<<nblocks, 256, SMEM_BYTES>>>(l, node_attr, anf, Wu1, bu1, Wu2, bu2);
    }

    cudaMemsetAsync(poolp, 0, (size_t)BB * HH * sizeof(float));
    cudaMemsetAsync(cntp, 0, (size_t)BB * sizeof(float));
    pool_kernel<<<nblocks, 256, SMEM_BYTES>>>(node_attr, batch, Wp1, bp1, Wp2, bp2);
    final_kernel<<<1, BB>>>(Wq1, bq1, Wq2, bq2, out);
}

// round 2
// speedup vs baseline: 1.4524x; 1.4524x over previous
#include <cuda_runtime.h>
#include <math.h>

#define NN 10000
#define EE 160000
#define BB 16
#define HH 64
#define AA 8
#define LL 2
#define MSGIN 131
#define UPDIN 129

// ---------------- scratch (device globals: no allocation allowed) ----------
__device__ float g_h[NN * HH];
__device__ float g_agg[NN * HH];
__device__ float g_pool[BB * HH];
__device__ float g_cnt[BB];
__device__ float g_T1[NN * 512];   // T1[n, k*8+j] = sum_i haug[n,i] W1[i,j,k]
__device__ float g_T2[NN * 512];   // rows 65..129

__device__ __forceinline__ float silu_f(float x) { return x / (1.0f + expf(-x)); }

// ========== OLD layout (embed / upd / pool kernels) =========================
#define OFF_SW   0
#define OFF_SIN  16384
#define OFF_SMID (16384 + 8448)
#define OFF_SA   (16384 + 8448 + 16640)
#define OFF_SIDX (OFF_SA + 2048)
#define SMEM_FLOATS (OFF_SIDX + 512)
#define SMEM_BYTES (SMEM_FLOATS * 4)

__device__ __forceinline__ void tp_accum(float (&acc)[4][16], const float* s_in, int stride,
                                         const float* s_W, const float (&av)[4][8],
                                         int e0, int kbase, int ilen)
{
    for (int i = 0; i < ilen; ++i) {
        float m0 = s_in[(e0 + 0) * stride + i];
        float m1 = s_in[(e0 + 1) * stride + i];
        float m2 = s_in[(e0 + 2) * stride + i];
        float m3 = s_in[(e0 + 3) * stride + i];
        const float* wrow = s_W + i * 512 + kbase;
#pragma unroll
        for (int j = 0; j < 8; ++j) {
            float4 wa = *(const float4*)(wrow + j * 64);
            float4 wb = *(const float4*)(wrow + j * 64 + 4);
            float4 wc = *(const float4*)(wrow + j * 64 + 8);
            float4 wd = *(const float4*)(wrow + j * 64 + 12);
            float w[16] = {wa.x, wa.y, wa.z, wa.w, wb.x, wb.y, wb.z, wb.w,
                           wc.x, wc.y, wc.z, wc.w, wd.x, wd.y, wd.z, wd.w};
            float c0 = m0 * av[0][j];
            float c1 = m1 * av[1][j];
            float c2 = m2 * av[2][j];
            float c3 = m3 * av[3][j];
#pragma unroll
            for (int k = 0; k < 16; ++k) {
                acc[0][k] = fmaf(c0, w[k], acc[0][k]);
                acc[1][k] = fmaf(c1, w[k], acc[1][k]);
                acc[2][k] = fmaf(c2, w[k], acc[2][k]);
                acc[3][k] = fmaf(c3, w[k], acc[3][k]);
            }
        }
    }
}

__device__ __forceinline__ void load_w_tile(float* s_W, const float* Wg, int ibase, int ilen)
{
    const float4* src = (const float4*)(Wg + (size_t)ibase * 512);
    float4* dst = (float4*)s_W;
    int n4 = ilen * 128;
    for (int idx = threadIdx.x; idx < n4; idx += 256) dst[idx] = src[idx];
}

// ================= nodeT kernel: T1/T2 = h_aug @ W1-blocks (k-major out) ====
// smem: s_Wt 65*128 = 8320 floats, s_h 64*65 = 4160 floats
#define NT_OFF_W 0
#define NT_OFF_H 8320
#define NT_FLOATS (8320 + 4160)
#define NT_BYTES (NT_FLOATS * 4)

__global__ void __launch_bounds__(256, 2)
nodeT_kernel(int l, const float* __restrict__ anf, const float* __restrict__ Wm1)
{
    extern __shared__ float sm[];
    float* s_Wt = sm + NT_OFF_W;
    float* s_h  = sm + NT_OFF_H;

    int tid = threadIdx.x;
    int n0 = blockIdx.x * 64;
    const float* Wl = Wm1 + (size_t)l * MSGIN * 512;

    // stage h_aug for 64 nodes
    for (int idx = tid; idx < 64 * 65; idx += 256) {
        int node = idx / 65, i = idx - node * 65;
        int n = min(n0 + node, NN - 1);
        s_h[idx] = (i < 64) ? g_h[n * 64 + i] : anf[n];
    }

    int nq = tid >> 2;          // node 0..63
    int cq = tid & 3;           // col quarter

    for (int cc = 0; cc < 8; ++cc) {
        int is_t1 = (cc < 4);
        int base_row = is_t1 ? 0 : 65;
        int c_base = (is_t1 ? cc : cc - 4) * 128;

        __syncthreads();
        for (int idx = tid; idx < 65 * 128; idx += 256) {
            int i = idx >> 7, cl = idx & 127;
            int c = c_base + cl;
            int j = c & 7, k = c >> 3;
            s_Wt[idx] = Wl[(size_t)(base_row + i) * 512 + j * 64 + k];
        }
        __syncthreads();

        float acc[32];
#pragma unroll
        for (int t = 0; t < 32; ++t) acc[t] = 0.0f;

        for (int i = 0; i < 65; ++i) {
            float h = s_h[nq * 65 + i];
            const float* wrow = s_Wt + i * 128;
#pragma unroll
            for (int t = 0; t < 8; ++t) {
                float4 w = *(const float4*)(wrow + (cq + 4 * t) * 4);
                acc[t * 4 + 0] = fmaf(h, w.x, acc[t * 4 + 0]);
                acc[t * 4 + 1] = fmaf(h, w.y, acc[t * 4 + 1]);
                acc[t * 4 + 2] = fmaf(h, w.z, acc[t * 4 + 2]);
                acc[t * 4 + 3] = fmaf(h, w.w, acc[t * 4 + 3]);
            }
        }

        int n = n0 + nq;
        if (n < NN) {
            float* dstp = (is_t1 ? g_T1 : g_T2) + (size_t)n * 512 + c_base;
#pragma unroll
            for (int t = 0; t < 8; ++t) {
                *(float4*)(dstp + (cq + 4 * t) * 4) =
                    make_float4(acc[t * 4 + 0], acc[t * 4 + 1], acc[t * 4 + 2], acc[t * 4 + 3]);
            }
        }
    }
}

// ================= msg kernel v2: factored TP1 + fused TP2 + scatter ========
// tile = 128 edges, 256 threads, 2 CTAs/SM
// smem floats:
#define M2_OFF_W    0          // 16*512 = 8192
#define M2_OFF_M1   8192       // 128*65 = 8320
#define M2_OFF_A    16512      // 128*8  = 1024
#define M2_OFF_WAMF 17536      // 512
#define M2_OFF_B1   18048      // 64
#define M2_OFF_B2   18112      // 64
#define M2_OFF_IDX  18176      // 256 ints (src 128 | dst 128)
#define M2_FLOATS   18432
#define M2_BYTES    (M2_FLOATS * 4)

__global__ void __launch_bounds__(256, 2)
msg_kernel_v2(int l, const int* __restrict__ edge_index, const float* __restrict__ edge_attr,
              const float* __restrict__ amf,
              const float* __restrict__ Wm1, const float* __restrict__ bm1,
              const float* __restrict__ Wm2, const float* __restrict__ bm2)
{
    extern __shared__ float sm[];
    float* s_W2   = sm + M2_OFF_W;
    float* s_m1   = sm + M2_OFF_M1;
    float* s_a    = sm + M2_OFF_A;
    float* s_wamf = sm + M2_OFF_WAMF;
    float* s_b1   = sm + M2_OFF_B1;
    float* s_b2   = sm + M2_OFF_B2;
    int*   s_src  = (int*)(sm + M2_OFF_IDX);
    int*   s_dst  = s_src + 128;

    int tid = threadIdx.x;
    int e_abs0 = blockIdx.x * 128;
    const float* W1l = Wm1 + (size_t)l * MSGIN * 512;
    const float* W2l = Wm2 + (size_t)l * 64 * 512;

    if (tid < 128) {
        s_src[tid] = edge_index[e_abs0 + tid];
        s_dst[tid] = edge_index[EE + e_abs0 + tid];
    }
    for (int idx = tid; idx < 1024; idx += 256)
        s_a[idx] = edge_attr[(size_t)e_abs0 * 8 + idx];
    for (int idx = tid; idx < 512; idx += 256) {
        int k = idx >> 3, j = idx & 7;
        s_wamf[idx] = W1l[(size_t)130 * 512 + j * 64 + k];
    }
    if (tid < 64) {
        s_b1[tid] = bm1[l * 64 + tid];
        s_b2[tid] = bm2[l * 64 + tid];
    }
    __syncthreads();

    // ---- Phase A: m1[e,k] = silu(b1 + sum_j a_j*(T1[d]+T2[s]) + amf*sum_j a_j*Wamf)
    {
        int e = tid >> 1;            // edge 0..127
        int kh = tid & 1;            // k-half
        int k0 = kh * 32;
        int d  = s_dst[e];
        int sn = s_src[e];
        float amfv = amf[e_abs0 + e];
        float a[8], am[8];
#pragma unroll
        for (int j = 0; j < 8; ++j) {
            a[j] = s_a[e * 8 + j];
            am[j] = a[j] * amfv;
        }
        const float4* T1p = (const float4*)(g_T1 + (size_t)d * 512 + k0 * 8);
        const float4* T2p = (const float4*)(g_T2 + (size_t)sn * 512 + k0 * 8);
        const float4* Wam = (const float4*)(s_wamf + k0 * 8);

#pragma unroll 8
        for (int kk = 0; kk < 32; ++kk) {
            float4 p0 = T1p[kk * 2], p1 = T1p[kk * 2 + 1];
            float4 q0 = T2p[kk * 2], q1 = T2p[kk * 2 + 1];
            float4 w0 = Wam[kk * 2], w1 = Wam[kk * 2 + 1];
            float r = s_b1[k0 + kk];
            r = fmaf(a[0], p0.x + q0.x, r);
            r = fmaf(a[1], p0.y + q0.y, r);
            r = fmaf(a[2], p0.z + q0.z, r);
            r = fmaf(a[3], p0.w + q0.w, r);
            r = fmaf(a[4], p1.x + q1.x, r);
            r = fmaf(a[5], p1.y + q1.y, r);
            r = fmaf(a[6], p1.z + q1.z, r);
            r = fmaf(a[7], p1.w + q1.w, r);
            r = fmaf(am[0], w0.x, r);
            r = fmaf(am[1], w0.y, r);
            r = fmaf(am[2], w0.z, r);
            r = fmaf(am[3], w0.w, r);
            r = fmaf(am[4], w1.x, r);
            r = fmaf(am[5], w1.y, r);
            r = fmaf(am[6], w1.z, r);
            r = fmaf(am[7], w1.w, r);
            s_m1[e * 65 + k0 + kk] = silu_f(r);
        }
    }
    __syncthreads();

    // ---- Phase B: TP2 (m1, edge_attr, W2) -> silu -> atomic scatter to agg[dst]
    int eg = tid >> 3;           // 0..31 -> 4 edges each
    int kg = tid & 7;            // 8 k each
    int e0 = eg * 4;
    int kbase = kg * 8;

    float av[4][8];
#pragma unroll
    for (int s = 0; s < 4; ++s)
#pragma unroll
        for (int j = 0; j < 8; ++j) av[s][j] = s_a[(e0 + s) * 8 + j];

    float acc[4][8];
#pragma unroll
    for (int t = 0; t < 8; ++t) {
        float b = s_b2[kbase + t];
        acc[0][t] = b; acc[1][t] = b; acc[2][t] = b; acc[3][t] = b;
    }

    for (int ibase = 0; ibase < 64; ibase += 16) {
        // stage 16 x 512 W2 tile
        {
            const float4* srcw = (const float4*)(W2l + (size_t)ibase * 512);
            float4* dstw = (float4*)s_W2;
            for (int idx = tid; idx < 16 * 128; idx += 256) dstw[idx] = srcw[idx];
        }
        __syncthreads();

        for (int i = 0; i < 16; ++i) {
            float m0 = s_m1[(e0 + 0) * 65 + ibase + i];
            float m1v = s_m1[(e0 + 1) * 65 + ibase + i];
            float m2 = s_m1[(e0 + 2) * 65 + ibase + i];
            float m3 = s_m1[(e0 + 3) * 65 + ibase + i];
            const float* wrow = s_W2 + i * 512 + kbase;
#pragma unroll
            for (int j = 0; j < 8; ++j) {
                float4 wa = *(const float4*)(wrow + j * 64);
                float4 wb = *(const float4*)(wrow + j * 64 + 4);
                float w[8] = {wa.x, wa.y, wa.z, wa.w, wb.x, wb.y, wb.z, wb.w};
                float c0 = m0  * av[0][j];
                float c1 = m1v * av[1][j];
                float c2 = m2  * av[2][j];
                float c3 = m3  * av[3][j];
#pragma unroll
                for (int t = 0; t < 8; ++t) {
                    acc[0][t] = fmaf(c0, w[t], acc[0][t]);
                    acc[1][t] = fmaf(c1, w[t], acc[1][t]);
                    acc[2][t] = fmaf(c2, w[t], acc[2][t]);
                    acc[3][t] = fmaf(c3, w[t], acc[3][t]);
                }
            }
        }
        __syncthreads();
    }

#pragma unroll
    for (int s = 0; s < 4; ++s) {
        int nd = s_dst[e0 + s];
#pragma unroll
        for (int t = 0; t < 8; ++t)
            atomicAdd(&g_agg[nd * 64 + kbase + t], silu_f(acc[s][t]));
    }
}

// ---------------- embedding kernel: h = TP17(concat(x,anf), node_attr) -----
__global__ void __launch_bounds__(256, 1)
embed_kernel(const float* __restrict__ x, const float* __restrict__ anf,
             const float* __restrict__ node_attr,
             const float* __restrict__ W_emb, const float* __restrict__ b_emb)
{
    extern __shared__ float sm[];
    float* s_W = sm + OFF_SW;
    float* s_in = sm + OFF_SIN;
    float* s_a = sm + OFF_SA;

    int tid = threadIdx.x;
    int n0 = blockIdx.x * 256;

    for (int idx = tid; idx < 2048; idx += 256) {
        int e = idx >> 3, j = idx & 7;
        int n = min(n0 + e, NN - 1);
        s_a[idx] = node_attr[n * 8 + j];
    }
    load_w_tile(s_W, W_emb, 0, 17);
    for (int idx = tid; idx < 256 * 17; idx += 256) {
        int e = idx / 17, i = idx - e * 17;
        int n = min(n0 + e, NN - 1);
        s_in[e * 33 + i] = (i < 16) ? x[n * 16 + i] : anf[n];
    }
    __syncthreads();

    int kg = tid & 3, ig = tid >> 2;
    int kbase = kg * 16, e0 = ig * 4;
    float av[4][8];
#pragma unroll
    for (int s = 0; s < 4; ++s)
#pragma unroll
        for (int j = 0; j < 8; ++j) av[s][j] = s_a[(e0 + s) * 8 + j];

    float acc[4][16];
#pragma unroll
    for (int k = 0; k < 16; ++k) {
        float b = b_emb[kbase + k];
        acc[0][k] = b; acc[1][k] = b; acc[2][k] = b; acc[3][k] = b;
    }
    tp_accum(acc, s_in, 33, s_W, av, e0, kbase, 17);

#pragma unroll
    for (int s = 0; s < 4; ++s) {
        int n = n0 + e0 + s;
        if (n < NN) {
#pragma unroll
            for (int k = 0; k < 16; ++k) g_h[n * 64 + kbase + k] = acc[s][k];
        }
    }
}

// ---------------- node update: silu(TP129) -> TP64, residual ---------------
__global__ void __launch_bounds__(256, 1)
upd_kernel(int l, const float* __restrict__ node_attr, const float* __restrict__ anf,
           const float* __restrict__ Wu1, const float* __restrict__ bu1,
           const float* __restrict__ Wu2, const float* __restrict__ bu2)
{
    extern __shared__ float sm[];
    float* s_W = sm + OFF_SW;
    float* s_in = sm + OFF_SIN;
    float* s_mid = sm + OFF_SMID;
    float* s_a = sm + OFF_SA;

    int tid = threadIdx.x;
    int n0 = blockIdx.x * 256;

    for (int idx = tid; idx < 2048; idx += 256) {
        int e = idx >> 3, j = idx & 7;
        int n = min(n0 + e, NN - 1);
        s_a[idx] = node_attr[n * 8 + j];
    }
    __syncthreads();

    int kg = tid & 3, ig = tid >> 2;
    int kbase = kg * 16, e0 = ig * 4;
    float av[4][8];
#pragma unroll
    for (int s = 0; s < 4; ++s)
#pragma unroll
        for (int j = 0; j < 8; ++j) av[s][j] = s_a[(e0 + s) * 8 + j];

    const float* W1 = Wu1 + (size_t)l * UPDIN * 512;
    const float* W2 = Wu2 + (size_t)l * 64 * 512;

    float acc[4][16];
#pragma unroll
    for (int k = 0; k < 16; ++k) {
        float b = bu1[l * 64 + kbase + k];
        acc[0][k] = b; acc[1][k] = b; acc[2][k] = b; acc[3][k] = b;
    }

    for (int ibase = 0; ibase < UPDIN; ibase += 32) {
        int ilen = min(32, UPDIN - ibase);
        load_w_tile(s_W, W1, ibase, ilen);
        for (int idx = tid; idx < 256 * ilen; idx += 256) {
            int e = idx / ilen, ii = idx - e * ilen;
            int i = ibase + ii;
            int n = min(n0 + e, NN - 1);
            float v;
            if (i < 64) v = g_h[n * 64 + i];
            else if (i == 64) v = anf[n];
            else v = g_agg[n * 64 + (i - 65)];
            s_in[e * 33 + ii] = v;
        }
        __syncthreads();
        tp_accum(acc, s_in, 33, s_W, av, e0, kbase, ilen);
        __syncthreads();
    }

#pragma unroll
    for (int s = 0; s < 4; ++s)
#pragma unroll
        for (int k = 0; k < 16; ++k)
            s_mid[(e0 + s) * 65 + kbase + k] = silu_f(acc[s][k]);
    __syncthreads();

#pragma unroll
    for (int k = 0; k < 16; ++k) {
        float b = bu2[l * 64 + kbase + k];
        acc[0][k] = b; acc[1][k] = b; acc[2][k] = b; acc[3][k] = b;
    }
    for (int ibase = 0; ibase < 64; ibase += 32) {
        load_w_tile(s_W, W2, ibase, 32);
        __syncthreads();
        tp_accum(acc, s_mid + ibase, 65, s_W, av, e0, kbase, 32);
        __syncthreads();
    }

#pragma unroll
    for (int s = 0; s < 4; ++s) {
        int n = n0 + e0 + s;
        if (n < NN) {
#pragma unroll
            for (int k = 0; k < 16; ++k)
                g_h[n * 64 + kbase + k] += acc[s][k];
        }
    }
}

// ---------------- pre-pool MLP + graph mean-pool scatter -------------------
__global__ void __launch_bounds__(256, 1)
pool_kernel(const float* __restrict__ node_attr, const int* __restrict__ batch,
            const float* __restrict__ Wp1, const float* __restrict__ bp1,
            const float* __restrict__ Wp2, const float* __restrict__ bp2)
{
    extern __shared__ float sm[];
    float* s_W = sm + OFF_SW;
    float* s_in = sm + OFF_SIN;
    float* s_mid = sm + OFF_SMID;
    float* s_a = sm + OFF_SA;

    int tid = threadIdx.x;
    int n0 = blockIdx.x * 256;

    for (int idx = tid; idx < 2048; idx += 256) {
        int e = idx >> 3, j = idx & 7;
        int n = min(n0 + e, NN - 1);
        s_a[idx] = node_attr[n * 8 + j];
    }
    __syncthreads();

    int kg = tid & 3, ig = tid >> 2;
    int kbase = kg * 16, e0 = ig * 4;
    float av[4][8];
#pragma unroll
    for (int s = 0; s < 4; ++s)
#pragma unroll
        for (int j = 0; j < 8; ++j) av[s][j] = s_a[(e0 + s) * 8 + j];

    float acc[4][16];
#pragma unroll
    for (int k = 0; k < 16; ++k) {
        float b = bp1[kbase + k];
        acc[0][k] = b; acc[1][k] = b; acc[2][k] = b; acc[3][k] = b;
    }
    for (int ibase = 0; ibase < 64; ibase += 32) {
        load_w_tile(s_W, Wp1, ibase, 32);
        for (int idx = tid; idx < 256 * 32; idx += 256) {
            int e = idx >> 5, ii = idx & 31;
            int n = min(n0 + e, NN - 1);
            s_in[e * 33 + ii] = g_h[n * 64 + ibase + ii];
        }
        __syncthreads();
        tp_accum(acc, s_in, 33, s_W, av, e0, kbase, 32);
        __syncthreads();
    }

#pragma unroll
    for (int s = 0; s < 4; ++s)
#pragma unroll
        for (int k = 0; k < 16; ++k)
            s_mid[(e0 + s) * 65 + kbase + k] = silu_f(acc[s][k]);
    __syncthreads();

#pragma unroll
    for (int k = 0; k < 16; ++k) {
        float b = bp2[kbase + k];
        acc[0][k] = b; acc[1][k] = b; acc[2][k] = b; acc[3][k] = b;
    }
    for (int ibase = 0; ibase < 64; ibase += 32) {
        load_w_tile(s_W, Wp2, ibase, 32);
        __syncthreads();
        tp_accum(acc, s_mid + ibase, 65, s_W, av, e0, kbase, 32);
        __syncthreads();
    }

#pragma unroll
    for (int s = 0; s < 4; ++s) {
        int n = n0 + e0 + s;
        if (n < NN) {
            int b = batch[n];
#pragma unroll
            for (int k = 0; k < 16; ++k)
                atomicAdd(&g_pool[b * 64 + kbase + k], acc[s][k]);
            if (kg == 0) atomicAdd(&g_cnt[b], 1.0f);
        }
    }
}

// ---------------- final tiny post-pool MLP ---------------------------------
__global__ void final_kernel(const float* __restrict__ Wq1, const float* __restrict__ bq1,
                             const float* __restrict__ Wq2, const float* __restrict__ bq2,
                             float* __restrict__ out)
{
    int b = threadIdx.x;
    if (b >= BB) return;
    float c = g_cnt[b];
    if (c < 1.0f) c = 1.0f;
    float g[64];
#pragma unroll
    for (int k = 0; k < 64; ++k) g[k] = g_pool[b * 64 + k] / c;
    float o = bq2[0];
    for (int j = 0; j < 64; ++j) {
        float s = bq1[j];
#pragma unroll
        for (int k = 0; k < 64; ++k) s = fmaf(g[k], Wq1[k * 64 + j], s);
        o = fmaf(silu_f(s), Wq2[j], o);
    }
    out[b] = o;
}

// ---------------- launch ----------------------------------------------------
extern "C" void kernel_launch(void* const* d_in, const int* in_sizes, int n_in,
                              void* d_out, int out_size)
{
    const float* x         = (const float*)d_in[0];
    const int*   edge_index= (const int*)d_in[1];
    const float* edge_attr = (const float*)d_in[2];
    const float* node_attr = (const float*)d_in[3];
    const float* amf       = (const float*)d_in[4];
    const float* anf       = (const float*)d_in[5];
    const int*   batch     = (const int*)d_in[6];
    const float* W_emb     = (const float*)d_in[7];
    const float* b_emb     = (const float*)d_in[8];
    const float* Wm1       = (const float*)d_in[9];
    const float* bm1       = (const float*)d_in[10];
    const float* Wm2       = (const float*)d_in[11];
    const float* bm2       = (const float*)d_in[12];
    const float* Wu1       = (const float*)d_in[13];
    const float* bu1       = (const float*)d_in[14];
    const float* Wu2       = (const float*)d_in[15];
    const float* bu2       = (const float*)d_in[16];
    const float* Wp1       = (const float*)d_in[17];
    const float* bp1       = (const float*)d_in[18];
    const float* Wp2       = (const float*)d_in[19];
    const float* bp2       = (const float*)d_in[20];
    const float* Wq1       = (const float*)d_in[21];
    const float* bq1       = (const float*)d_in[22];
    const float* Wq2       = (const float*)d_in[23];
    const float* bq2       = (const float*)d_in[24];
    float* out = (float*)d_out;

    cudaFuncSetAttribute(msg_kernel_v2, cudaFuncAttributeMaxDynamicSharedMemorySize, M2_BYTES);
    cudaFuncSetAttribute(nodeT_kernel,  cudaFuncAttributeMaxDynamicSharedMemorySize, NT_BYTES);
    cudaFuncSetAttribute(embed_kernel,  cudaFuncAttributeMaxDynamicSharedMemorySize, SMEM_BYTES);
    cudaFuncSetAttribute(upd_kernel,    cudaFuncAttributeMaxDynamicSharedMemorySize, SMEM_BYTES);
    cudaFuncSetAttribute(pool_kernel,   cudaFuncAttributeMaxDynamicSharedMemorySize, SMEM_BYTES);

    void* aggp = nullptr;  cudaGetSymbolAddress(&aggp, g_agg);
    void* poolp = nullptr; cudaGetSymbolAddress(&poolp, g_pool);
    void* cntp = nullptr;  cudaGetSymbolAddress(&cntp, g_cnt);

    int nblocks = (NN + 255) / 256;   // 40
    int tblocks = (NN + 63) / 64;     // 157
    int eblocks = EE / 128;           // 1250

    embed_kernel<<<nblocks, 256, SMEM_BYTES>>>(x, anf, node_attr, W_emb, b_emb);

    for (int l = 0; l < LL; ++l) {
        nodeT_kernel<<<tblocks, 256, NT_BYTES>>>(l, anf, Wm1);
        cudaMemsetAsync(aggp, 0, (size_t)NN * HH * sizeof(float));
        msg_kernel_v2<<<eblocks, 256, M2_BYTES>>>(l, edge_index, edge_attr, amf,
                                                  Wm1, bm1, Wm2, bm2);
        upd_kernel<<<nblocks, 256, SMEM_BYTES>>>(l, node_attr, anf, Wu1, bu1, Wu2, bu2);
    }

    cudaMemsetAsync(poolp, 0, (size_t)BB * HH * sizeof(float));
    cudaMemsetAsync(cntp, 0, (size_t)BB * sizeof(float));
    pool_kernel<<<nblocks, 256, SMEM_BYTES>>>(node_attr, batch, Wp1, bp1, Wp2, bp2);
    final_kernel<<<1, BB>>>(Wq1, bq1, Wq2, bq2, out);
}